// round 1
// baseline (speedup 1.0000x reference)
#include <cuda_runtime.h>
#include <cstdint>

// ============================================================================
// PoolBondFeatures:
//   out[e] = MLP([h[src],h[dst]]) + MLP([h[dst],h[src]])
// Decomposition:
//   AB[n] = h[n] @ [W1a | W1b]  (+b1 folded into A half)   -- phase 1, per NODE
//   out[e] = (relu(A[s]+B[d]) + relu(A[d]+B[s])) @ W2 + 2*b2  -- phase 2, per EDGE
// ============================================================================

#define D128 128
#define MAX_N 65536

// Scratch: per-node [A|B] rows, 256 floats each (64 MB static; no allocs).
__device__ float g_AB[(size_t)MAX_N * 256];

__device__ __forceinline__ unsigned long long pack2(float lo, float hi) {
    unsigned long long r;
    asm("mov.b64 %0, {%1, %2};" : "=l"(r) : "f"(lo), "f"(hi));
    return r;
}
__device__ __forceinline__ unsigned long long ffma2(unsigned long long a,
                                                    unsigned long long b,
                                                    unsigned long long c) {
    unsigned long long d;
    asm("fma.rn.f32x2 %0, %1, %2, %3;" : "=l"(d) : "l"(a), "l"(b), "l"(c));
    return d;
}

// ----------------------------------------------------------------------------
// Phase 1: AB[row, 0:128]  = h[row] @ W1[0:128]   + b1
//          AB[row,128:256] = h[row] @ W1[128:256]
// Tile: 64 rows x 256 cols per block, 256 threads, K chunked by 32.
// Per thread: 8 rows x 8 cols (as 4 f32x2 pairs: cols 4*tx..+3 and 128+4*tx..+3)
// ----------------------------------------------------------------------------
__global__ void __launch_bounds__(256, 2) phase1_kernel(
    const float* __restrict__ h, const float* __restrict__ W1,
    const float* __restrict__ b1, int N)
{
    __shared__ __align__(16) float hs[64 * 32];    // 8 KB
    __shared__ __align__(16) float Ws[32 * 256];   // 32 KB

    const int tid = threadIdx.x;
    const int tx = tid & 31;    // col group: cols {4tx..4tx+3} and {128+4tx..+3}
    const int ty = tid >> 5;    // row group: rows ty*8 .. ty*8+7
    const int row0 = blockIdx.x * 64;

    unsigned long long acc[8][4];
    {
        float4 bv = *(const float4*)&b1[4 * tx];
        #pragma unroll
        for (int i = 0; i < 8; i++) {
            acc[i][0] = pack2(bv.x, bv.y);
            acc[i][1] = pack2(bv.z, bv.w);
            acc[i][2] = 0ULL;   // (0.f, 0.f)
            acc[i][3] = 0ULL;
        }
    }

    for (int k0 = 0; k0 < 128; k0 += 32) {
        // load h tile: 64 rows x 32 k  (512 float4)
        #pragma unroll
        for (int it = 0; it < 2; it++) {
            int idx4 = tid + it * 256;
            int r = idx4 >> 3;
            int kq = idx4 & 7;
            int row = row0 + r;
            if (row > N - 1) row = N - 1;
            *(float4*)&hs[r * 32 + kq * 4] =
                *(const float4*)&h[(size_t)row * D128 + k0 + kq * 4];
        }
        // load Wcat chunk: 32 k x 256 cols (2048 float4)
        // Wcat[k, jp] = jp<128 ? W1[k0+k][jp] : W1[128+k0+k][jp-128]
        #pragma unroll
        for (int it = 0; it < 8; it++) {
            int idx4 = tid + it * 256;
            int lin = idx4 * 4;
            int k = lin >> 8;
            int jp = lin & 255;
            const float* sw = (jp < 128)
                ? (W1 + (size_t)(k0 + k) * D128 + jp)
                : (W1 + (size_t)(128 + k0 + k) * D128 + (jp - 128));
            *(float4*)&Ws[k * 256 + jp] = *(const float4*)sw;
        }
        __syncthreads();

        #pragma unroll
        for (int kk = 0; kk < 32; kk += 2) {
            ulonglong2 w00 = *(const ulonglong2*)&Ws[kk * 256 + 4 * tx];
            ulonglong2 w01 = *(const ulonglong2*)&Ws[kk * 256 + 128 + 4 * tx];
            ulonglong2 w10 = *(const ulonglong2*)&Ws[(kk + 1) * 256 + 4 * tx];
            ulonglong2 w11 = *(const ulonglong2*)&Ws[(kk + 1) * 256 + 128 + 4 * tx];
            #pragma unroll
            for (int i = 0; i < 8; i++) {
                float2 a = *(const float2*)&hs[(ty * 8 + i) * 32 + kk];
                unsigned long long a0 = pack2(a.x, a.x);
                acc[i][0] = ffma2(a0, w00.x, acc[i][0]);
                acc[i][1] = ffma2(a0, w00.y, acc[i][1]);
                acc[i][2] = ffma2(a0, w01.x, acc[i][2]);
                acc[i][3] = ffma2(a0, w01.y, acc[i][3]);
                unsigned long long a1 = pack2(a.y, a.y);
                acc[i][0] = ffma2(a1, w10.x, acc[i][0]);
                acc[i][1] = ffma2(a1, w10.y, acc[i][1]);
                acc[i][2] = ffma2(a1, w11.x, acc[i][2]);
                acc[i][3] = ffma2(a1, w11.y, acc[i][3]);
            }
        }
        __syncthreads();
    }

    #pragma unroll
    for (int i = 0; i < 8; i++) {
        int row = row0 + ty * 8 + i;
        if (row < N) {
            ulonglong2 v0; v0.x = acc[i][0]; v0.y = acc[i][1];
            *(ulonglong2*)&g_AB[(size_t)row * 256 + 4 * tx] = v0;
            ulonglong2 v1; v1.x = acc[i][2]; v1.y = acc[i][3];
            *(ulonglong2*)&g_AB[(size_t)row * 256 + 128 + 4 * tx] = v1;
        }
    }
}

// ----------------------------------------------------------------------------
// Phase 2: per 64-edge tile:
//   S[e] = relu(A[s]+B[d]) + relu(A[d]+B[s])   (gather from g_AB, L2-resident)
//   out[e] = S[e] @ W2 + 2*b2
// 256 threads; GEMM thread tile: 4 edges x 8 cols (cols 4tx..+3, 64+4tx..+3).
// ----------------------------------------------------------------------------
__global__ void __launch_bounds__(256) phase2_kernel(
    const void* __restrict__ srcp, const void* __restrict__ dstp,
    const float* __restrict__ W2, const float* __restrict__ b2,
    float* __restrict__ out, int E)
{
    __shared__ __align__(16) float S[64 * 128];     // 32 KB
    __shared__ __align__(16) float W2s[16 * 128];   // 8 KB
    __shared__ int sidx[64];
    __shared__ int didx[64];

    const int tid = threadIdx.x;
    const int tile0 = blockIdx.x * 64;

    // dtype sniff: jax "int64" indices may actually be int32 (x64 disabled).
    // int64 data: all values < N << 2^31. int32 data reinterpreted as int64
    // has random high words -> huge values. Check first 4.
    const long long* s64 = (const long long*)srcp;
    const int* s32 = (const int*)srcp;
    const long long* d64 = (const long long*)dstp;
    const int* d32 = (const int*)dstp;
    unsigned long long m = (unsigned long long)(s64[0] | s64[1] | s64[2] | s64[3]);
    const bool idx64 = (m >> 31) == 0ULL;

    if (tid < 64) {
        int e = tile0 + tid;
        if (e >= E) e = 0;
        sidx[tid] = idx64 ? (int)s64[e] : s32[e];
    } else if (tid < 128) {
        int t = tid - 64;
        int e = tile0 + t;
        if (e >= E) e = 0;
        didx[t] = idx64 ? (int)d64[e] : d32[e];
    }
    __syncthreads();

    // Gather + relu-sum: warp w handles edges w*8..w*8+7; lane l covers cols 4l..4l+3
    {
        const int w = tid >> 5, l = tid & 31;
        #pragma unroll
        for (int i = 0; i < 8; i++) {
            int e = w * 8 + i;
            size_t sb = (size_t)sidx[e] * 256;
            size_t db = (size_t)didx[e] * 256;
            float4 As = *(const float4*)&g_AB[sb + 4 * l];
            float4 Bs = *(const float4*)&g_AB[sb + 128 + 4 * l];
            float4 Ad = *(const float4*)&g_AB[db + 4 * l];
            float4 Bd = *(const float4*)&g_AB[db + 128 + 4 * l];
            float4 r;
            r.x = fmaxf(As.x + Bd.x, 0.f) + fmaxf(Ad.x + Bs.x, 0.f);
            r.y = fmaxf(As.y + Bd.y, 0.f) + fmaxf(Ad.y + Bs.y, 0.f);
            r.z = fmaxf(As.z + Bd.z, 0.f) + fmaxf(Ad.z + Bs.z, 0.f);
            r.w = fmaxf(As.w + Bd.w, 0.f) + fmaxf(Ad.w + Bs.w, 0.f);
            *(float4*)&S[e * 128 + 4 * l] = r;
        }
    }
    __syncthreads();

    // GEMM: out_tile[64,128] = S @ W2 + 2*b2
    const int tx = tid & 15;   // cols {4tx..4tx+3} and {64+4tx..+3}
    const int ty = tid >> 4;   // edges ty*4 .. ty*4+3
    unsigned long long acc[4][4];
    {
        float4 bv0 = *(const float4*)&b2[4 * tx];
        float4 bv1 = *(const float4*)&b2[64 + 4 * tx];
        #pragma unroll
        for (int i = 0; i < 4; i++) {
            acc[i][0] = pack2(2.f * bv0.x, 2.f * bv0.y);
            acc[i][1] = pack2(2.f * bv0.z, 2.f * bv0.w);
            acc[i][2] = pack2(2.f * bv1.x, 2.f * bv1.y);
            acc[i][3] = pack2(2.f * bv1.z, 2.f * bv1.w);
        }
    }

    for (int k0 = 0; k0 < 128; k0 += 16) {
        // load W2 chunk: 16 k x 128 cols (512 float4)
        #pragma unroll
        for (int it = 0; it < 2; it++) {
            int idx4 = tid + it * 256;
            int lin = idx4 * 4;
            int k = lin >> 7;
            int jp = lin & 127;
            *(float4*)&W2s[k * 128 + jp] =
                *(const float4*)&W2[(size_t)(k0 + k) * D128 + jp];
        }
        __syncthreads();

        #pragma unroll
        for (int kk = 0; kk < 16; kk += 2) {
            ulonglong2 w00 = *(const ulonglong2*)&W2s[kk * 128 + 4 * tx];
            ulonglong2 w01 = *(const ulonglong2*)&W2s[kk * 128 + 64 + 4 * tx];
            ulonglong2 w10 = *(const ulonglong2*)&W2s[(kk + 1) * 128 + 4 * tx];
            ulonglong2 w11 = *(const ulonglong2*)&W2s[(kk + 1) * 128 + 64 + 4 * tx];
            #pragma unroll
            for (int i = 0; i < 4; i++) {
                float2 a = *(const float2*)&S[(ty * 4 + i) * 128 + k0 + kk];
                unsigned long long a0 = pack2(a.x, a.x);
                acc[i][0] = ffma2(a0, w00.x, acc[i][0]);
                acc[i][1] = ffma2(a0, w00.y, acc[i][1]);
                acc[i][2] = ffma2(a0, w01.x, acc[i][2]);
                acc[i][3] = ffma2(a0, w01.y, acc[i][3]);
                unsigned long long a1 = pack2(a.y, a.y);
                acc[i][0] = ffma2(a1, w10.x, acc[i][0]);
                acc[i][1] = ffma2(a1, w10.y, acc[i][1]);
                acc[i][2] = ffma2(a1, w11.x, acc[i][2]);
                acc[i][3] = ffma2(a1, w11.y, acc[i][3]);
            }
        }
        __syncthreads();
    }

    #pragma unroll
    for (int i = 0; i < 4; i++) {
        int eg = tile0 + ty * 4 + i;
        if (eg < E) {
            ulonglong2 v0; v0.x = acc[i][0]; v0.y = acc[i][1];
            *(ulonglong2*)&out[(size_t)eg * D128 + 4 * tx] = v0;
            ulonglong2 v1; v1.x = acc[i][2]; v1.y = acc[i][3];
            *(ulonglong2*)&out[(size_t)eg * D128 + 64 + 4 * tx] = v1;
        }
    }
}

// ----------------------------------------------------------------------------
extern "C" void kernel_launch(void* const* d_in, const int* in_sizes, int n_in,
                              void* d_out, int out_size) {
    const float* h  = (const float*)d_in[0];
    const void*  sp = d_in[1];
    const void*  dp = d_in[2];
    const float* W1 = (const float*)d_in[3];
    const float* b1 = (const float*)d_in[4];
    const float* W2 = (const float*)d_in[5];
    const float* b2 = (const float*)d_in[6];
    float* out = (float*)d_out;

    int N = in_sizes[0] / D128;   // 50000
    int E = in_sizes[1];          // 500000 (element count, dtype-independent)
    if (N > MAX_N) N = MAX_N;

    int g1 = (N + 63) / 64;
    phase1_kernel<<<g1, 256>>>(h, W1, b1, N);

    int g2 = (E + 63) / 64;
    phase2_kernel<<<g2, 256>>>(sp, dp, W2, b2, out, E);

    (void)n_in; (void)out_size;
}